// round 1
// baseline (speedup 1.0000x reference)
#include <cuda_runtime.h>

#define Bv 64
#define Sv 256
#define Hv 768
#define Tv 13
#define Dv 64
#define NQK 1664          /* T*2*D */
#define M1 16384          /* B*S */
#define NEGC 1000000000000.0f

// Scratch: RoPE'd q|k interleaved, layout [M1][NQK] (head h: cols h*128 .. h*128+127, q first 64, k next 64)
__device__ float g_qk[M1 * NQK];
__device__ float g_sin[Sv * Dv];
__device__ float g_cos[Sv * Dv];

// ---------------------------------------------------------------------------
// RoPE table: pre-repeated (cos/sin value duplicated for d=2i and d=2i+1)
// ---------------------------------------------------------------------------
__global__ void rope_init_kernel() {
    int idx = blockIdx.x * blockDim.x + threadIdx.x;
    if (idx >= Sv * Dv) return;
    int s = idx / Dv;
    int d = idx % Dv;
    int i = d >> 1;
    float inv = powf(10000.0f, -2.0f * (float)i / (float)Dv);
    float ang = (float)s * inv;
    g_sin[idx] = sinf(ang);
    g_cos[idx] = cosf(ang);
}

// ---------------------------------------------------------------------------
// GEMM1 + bias + RoPE epilogue.
// C[16384,1664] = X[16384,768] @ W[768,1664] + b, then RoPE along d within
// each 64-wide half of every 128-wide head column block.
// Block tile 128x128, K-chunk 16, 256 threads, 8x8 per thread (4+4 split).
// ---------------------------------------------------------------------------
__global__ __launch_bounds__(256) void gemm1_rope_kernel(
    const float* __restrict__ X,
    const float* __restrict__ W,
    const float* __restrict__ bias)
{
    __shared__ float As[2][16][132];   // [k][m], padded row
    __shared__ float Bs[2][16][128];   // [k][n]

    const int bn = blockIdx.x;         // 0..12  (head)
    const int bm = blockIdx.y;         // 0..127
    const int tid = threadIdx.x;
    const int tx = tid & 15;
    const int ty = tid >> 4;

    const float* Ablk = X + (size_t)bm * 128 * Hv;
    const float* Bblk = W + bn * 128;

    const int ra = tid >> 1;           // A: row 0..127
    const int ka = (tid & 1) * 8;      // A: k offset 0 or 8
    const int rb = tid >> 4;           // B: k row 0..15
    const int cb = (tid & 15) * 8;     // B: col 0..120

    float acc[8][8];
    #pragma unroll
    for (int i = 0; i < 8; ++i)
        #pragma unroll
        for (int j = 0; j < 8; ++j) acc[i][j] = 0.f;

    float4 ald0, ald1, bld0, bld1;

    // prefetch chunk 0
    {
        const float* ap = Ablk + ra * Hv + ka;
        ald0 = *(const float4*)(ap);
        ald1 = *(const float4*)(ap + 4);
        const float* bp = Bblk + (size_t)rb * NQK + cb;
        bld0 = *(const float4*)(bp);
        bld1 = *(const float4*)(bp + 4);
    }
    // store chunk 0 -> buf 0
    {
        As[0][ka + 0][ra] = ald0.x; As[0][ka + 1][ra] = ald0.y;
        As[0][ka + 2][ra] = ald0.z; As[0][ka + 3][ra] = ald0.w;
        As[0][ka + 4][ra] = ald1.x; As[0][ka + 5][ra] = ald1.y;
        As[0][ka + 6][ra] = ald1.z; As[0][ka + 7][ra] = ald1.w;
        *(float4*)&Bs[0][rb][cb] = bld0;
        *(float4*)&Bs[0][rb][cb + 4] = bld1;
    }
    __syncthreads();

    const int nChunks = Hv / 16;       // 48
    for (int t = 0; t < nChunks; ++t) {
        const int buf = t & 1;
        if (t + 1 < nChunks) {
            const int k0 = (t + 1) * 16;
            const float* ap = Ablk + ra * Hv + k0 + ka;
            ald0 = *(const float4*)(ap);
            ald1 = *(const float4*)(ap + 4);
            const float* bp = Bblk + (size_t)(k0 + rb) * NQK + cb;
            bld0 = *(const float4*)(bp);
            bld1 = *(const float4*)(bp + 4);
        }
        #pragma unroll
        for (int kk = 0; kk < 16; ++kk) {
            float a[8], b[8];
            *(float4*)&a[0] = *(float4*)&As[buf][kk][ty * 4];
            *(float4*)&a[4] = *(float4*)&As[buf][kk][64 + ty * 4];
            *(float4*)&b[0] = *(float4*)&Bs[buf][kk][tx * 4];
            *(float4*)&b[4] = *(float4*)&Bs[buf][kk][64 + tx * 4];
            #pragma unroll
            for (int i = 0; i < 8; ++i)
                #pragma unroll
                for (int j = 0; j < 8; ++j)
                    acc[i][j] = fmaf(a[i], b[j], acc[i][j]);
        }
        if (t + 1 < nChunks) {
            const int nb = buf ^ 1;
            As[nb][ka + 0][ra] = ald0.x; As[nb][ka + 1][ra] = ald0.y;
            As[nb][ka + 2][ra] = ald0.z; As[nb][ka + 3][ra] = ald0.w;
            As[nb][ka + 4][ra] = ald1.x; As[nb][ka + 5][ra] = ald1.y;
            As[nb][ka + 6][ra] = ald1.z; As[nb][ka + 7][ra] = ald1.w;
            *(float4*)&Bs[nb][rb][cb] = bld0;
            *(float4*)&Bs[nb][rb][cb + 4] = bld1;
        }
        __syncthreads();
    }

    // ---- epilogue: bias + RoPE, write to g_qk ----
    const int colbase = bn * 128;
    const int rowbase = bm * 128;

    float bc[8];
    #pragma unroll
    for (int j = 0; j < 8; ++j) {
        int c = (j < 4) ? (tx * 4 + j) : (64 + tx * 4 + (j - 4));
        bc[j] = bias[colbase + c];
    }
    const int dbase = tx * 4;   // d index (same for both halves)

    #pragma unroll
    for (int r = 0; r < 8; ++r) {
        const int rl = (r < 4) ? (ty * 4 + r) : (64 + ty * 4 + (r - 4));
        const int m = rowbase + rl;
        const int s = m & (Sv - 1);
        float4 cs = *(const float4*)&g_cos[s * Dv + dbase];
        float4 sn = *(const float4*)&g_sin[s * Dv + dbase];
        #pragma unroll
        for (int g = 0; g < 2; ++g) {
            float v0 = acc[r][g * 4 + 0] + bc[g * 4 + 0];
            float v1 = acc[r][g * 4 + 1] + bc[g * 4 + 1];
            float v2 = acc[r][g * 4 + 2] + bc[g * 4 + 2];
            float v3 = acc[r][g * 4 + 3] + bc[g * 4 + 3];
            float4 o;
            o.x = v0 * cs.x - v1 * sn.x;
            o.y = v1 * cs.y + v0 * sn.y;
            o.z = v2 * cs.z - v3 * sn.z;
            o.w = v3 * cs.w + v2 * sn.w;
            *(float4*)&g_qk[(size_t)m * NQK + colbase + g * 64 + tx * 4] = o;
        }
    }
}

// ---------------------------------------------------------------------------
// GEMM2: per (b,h) logits[m,n] = sum_d q[m,d]*k[n,d], fused mask epilogue.
// Grid (nt=2, mt=2, b*13+h). 128x128 tile, K=64 in two 32-deep smem chunks.
// ---------------------------------------------------------------------------
__global__ __launch_bounds__(256) void attn_mask_kernel(
    const float* __restrict__ mask,
    float* __restrict__ out)
{
    __shared__ float Qs[32][128];      // [k][m]
    __shared__ float Ks[32][128];      // [k][n]

    const int bh = blockIdx.z;         // b*13 + h
    const int b  = bh / Tv;
    const int h  = bh - b * Tv;
    const int mt = blockIdx.y;
    const int nt = blockIdx.x;
    const int tid = threadIdx.x;
    const int tx = tid & 15;
    const int ty = tid >> 4;

    const int mrow_g = b * Sv + mt * 128;   // g_qk row base for Q
    const int nrow_g = b * Sv + nt * 128;   // g_qk row base for K
    const int qcol = h * 128;               // q at +0, k at +64

    float acc[8][8];
    #pragma unroll
    for (int i = 0; i < 8; ++i)
        #pragma unroll
        for (int j = 0; j < 8; ++j) acc[i][j] = 0.f;

    const int r  = tid >> 1;           // 0..127
    const int kh = (tid & 1) * 16;     // 0 or 16

    for (int k0 = 0; k0 < Dv; k0 += 32) {
        __syncthreads();
        const float* qp = g_qk + (size_t)(mrow_g + r) * NQK + qcol + k0 + kh;
        const float* kp = g_qk + (size_t)(nrow_g + r) * NQK + qcol + 64 + k0 + kh;
        #pragma unroll
        for (int u = 0; u < 4; ++u) {
            float4 qv = *(const float4*)(qp + u * 4);
            float4 kv = *(const float4*)(kp + u * 4);
            Qs[kh + u * 4 + 0][r] = qv.x; Qs[kh + u * 4 + 1][r] = qv.y;
            Qs[kh + u * 4 + 2][r] = qv.z; Qs[kh + u * 4 + 3][r] = qv.w;
            Ks[kh + u * 4 + 0][r] = kv.x; Ks[kh + u * 4 + 1][r] = kv.y;
            Ks[kh + u * 4 + 2][r] = kv.z; Ks[kh + u * 4 + 3][r] = kv.w;
        }
        __syncthreads();
        #pragma unroll
        for (int kk = 0; kk < 32; ++kk) {
            float a[8], bb[8];
            *(float4*)&a[0]  = *(float4*)&Qs[kk][ty * 4];
            *(float4*)&a[4]  = *(float4*)&Qs[kk][64 + ty * 4];
            *(float4*)&bb[0] = *(float4*)&Ks[kk][tx * 4];
            *(float4*)&bb[4] = *(float4*)&Ks[kk][64 + tx * 4];
            #pragma unroll
            for (int i = 0; i < 8; ++i)
                #pragma unroll
                for (int j = 0; j < 8; ++j)
                    acc[i][j] = fmaf(a[i], bb[j], acc[i][j]);
        }
    }

    // ---- epilogue: pad mask, causal (n < m), scale 1/8, matching ref op order ----
    int ncol[8];
    float pad[8];
    #pragma unroll
    for (int j = 0; j < 8; ++j) {
        int nl = (j < 4) ? (tx * 4 + j) : (64 + tx * 4 + (j - 4));
        ncol[j] = nt * 128 + nl;
        pad[j] = mask[b * Sv + ncol[j]];
    }

    #pragma unroll
    for (int i = 0; i < 8; ++i) {
        const int rl = (i < 4) ? (ty * 4 + i) : (64 + ty * 4 + (i - 4));
        const int m = mt * 128 + rl;
        float* op = out + ((size_t)bh * Sv + m) * Sv;
        float v[8];
        #pragma unroll
        for (int j = 0; j < 8; ++j) {
            float t = acc[i][j] * pad[j] - (1.0f - pad[j]) * NEGC;
            if (ncol[j] < m) t -= NEGC;
            v[j] = t * 0.125f;
        }
        float4 o0 = make_float4(v[0], v[1], v[2], v[3]);
        float4 o1 = make_float4(v[4], v[5], v[6], v[7]);
        *(float4*)(op + nt * 128 + tx * 4)      = o0;
        *(float4*)(op + nt * 128 + 64 + tx * 4) = o1;
    }
}

// ---------------------------------------------------------------------------
extern "C" void kernel_launch(void* const* d_in, const int* in_sizes, int n_in,
                              void* d_out, int out_size) {
    const float* X    = (const float*)d_in[0];   // last_hidden_state (64,256,768)
    const float* W    = (const float*)d_in[1];   // dense_w (768,1664)
    const float* bias = (const float*)d_in[2];   // dense_b (1664,)
    const float* mask = (const float*)d_in[3];   // attention_mask (64,256)
    float* out = (float*)d_out;                  // (64,13,256,256)

    rope_init_kernel<<<(Sv * Dv + 255) / 256, 256>>>();
    gemm1_rope_kernel<<<dim3(Tv, M1 / 128), 256>>>(X, W, bias);
    attn_mask_kernel<<<dim3(2, 2, Bv * Tv), 256>>>(mask, out);
}

// round 2
// speedup vs baseline: 1.0000x; 1.0000x over previous
#include <cuda_runtime.h>

#define Bv 64
#define Sv 256
#define Hv 768
#define Tv 13
#define Dv 64
#define NQK 1664          /* T*2*D */
#define M1 16384          /* B*S */
#define NEGC 1000000000000.0f

// Scratch: RoPE'd q|k interleaved, layout [M1][NQK] (head h: cols h*128 .. h*128+127, q first 64, k next 64)
__device__ float g_qk[M1 * NQK];
__device__ float g_sin[Sv * Dv];
__device__ float g_cos[Sv * Dv];

// ---------------------------------------------------------------------------
// RoPE table: pre-repeated (cos/sin value duplicated for d=2i and d=2i+1)
// ---------------------------------------------------------------------------
__global__ void rope_init_kernel() {
    int idx = blockIdx.x * blockDim.x + threadIdx.x;
    if (idx >= Sv * Dv) return;
    int s = idx / Dv;
    int d = idx % Dv;
    int i = d >> 1;
    float inv = powf(10000.0f, -2.0f * (float)i / (float)Dv);
    float ang = (float)s * inv;
    g_sin[idx] = sinf(ang);
    g_cos[idx] = cosf(ang);
}

// ---------------------------------------------------------------------------
// GEMM1 + bias + RoPE epilogue.
// C[16384,1664] = X[16384,768] @ W[768,1664] + b, then RoPE along d within
// each 64-wide half of every 128-wide head column block.
// Block tile 128x128, K-chunk 16, 256 threads, 8x8 per thread (4+4 split).
// ---------------------------------------------------------------------------
__global__ __launch_bounds__(256) void gemm1_rope_kernel(
    const float* __restrict__ X,
    const float* __restrict__ W,
    const float* __restrict__ bias)
{
    __shared__ float As[2][16][132];   // [k][m], padded row
    __shared__ float Bs[2][16][128];   // [k][n]

    const int bn = blockIdx.x;         // 0..12  (head)
    const int bm = blockIdx.y;         // 0..127
    const int tid = threadIdx.x;
    const int tx = tid & 15;
    const int ty = tid >> 4;

    const float* Ablk = X + (size_t)bm * 128 * Hv;
    const float* Bblk = W + bn * 128;

    const int ra = tid >> 1;           // A: row 0..127
    const int ka = (tid & 1) * 8;      // A: k offset 0 or 8
    const int rb = tid >> 4;           // B: k row 0..15
    const int cb = (tid & 15) * 8;     // B: col 0..120

    float acc[8][8];
    #pragma unroll
    for (int i = 0; i < 8; ++i)
        #pragma unroll
        for (int j = 0; j < 8; ++j) acc[i][j] = 0.f;

    float4 ald0, ald1, bld0, bld1;

    // prefetch chunk 0
    {
        const float* ap = Ablk + ra * Hv + ka;
        ald0 = *(const float4*)(ap);
        ald1 = *(const float4*)(ap + 4);
        const float* bp = Bblk + (size_t)rb * NQK + cb;
        bld0 = *(const float4*)(bp);
        bld1 = *(const float4*)(bp + 4);
    }
    // store chunk 0 -> buf 0
    {
        As[0][ka + 0][ra] = ald0.x; As[0][ka + 1][ra] = ald0.y;
        As[0][ka + 2][ra] = ald0.z; As[0][ka + 3][ra] = ald0.w;
        As[0][ka + 4][ra] = ald1.x; As[0][ka + 5][ra] = ald1.y;
        As[0][ka + 6][ra] = ald1.z; As[0][ka + 7][ra] = ald1.w;
        *(float4*)&Bs[0][rb][cb] = bld0;
        *(float4*)&Bs[0][rb][cb + 4] = bld1;
    }
    __syncthreads();

    const int nChunks = Hv / 16;       // 48
    for (int t = 0; t < nChunks; ++t) {
        const int buf = t & 1;
        if (t + 1 < nChunks) {
            const int k0 = (t + 1) * 16;
            const float* ap = Ablk + ra * Hv + k0 + ka;
            ald0 = *(const float4*)(ap);
            ald1 = *(const float4*)(ap + 4);
            const float* bp = Bblk + (size_t)(k0 + rb) * NQK + cb;
            bld0 = *(const float4*)(bp);
            bld1 = *(const float4*)(bp + 4);
        }
        #pragma unroll
        for (int kk = 0; kk < 16; ++kk) {
            float a[8], b[8];
            *(float4*)&a[0] = *(float4*)&As[buf][kk][ty * 4];
            *(float4*)&a[4] = *(float4*)&As[buf][kk][64 + ty * 4];
            *(float4*)&b[0] = *(float4*)&Bs[buf][kk][tx * 4];
            *(float4*)&b[4] = *(float4*)&Bs[buf][kk][64 + tx * 4];
            #pragma unroll
            for (int i = 0; i < 8; ++i)
                #pragma unroll
                for (int j = 0; j < 8; ++j)
                    acc[i][j] = fmaf(a[i], b[j], acc[i][j]);
        }
        if (t + 1 < nChunks) {
            const int nb = buf ^ 1;
            As[nb][ka + 0][ra] = ald0.x; As[nb][ka + 1][ra] = ald0.y;
            As[nb][ka + 2][ra] = ald0.z; As[nb][ka + 3][ra] = ald0.w;
            As[nb][ka + 4][ra] = ald1.x; As[nb][ka + 5][ra] = ald1.y;
            As[nb][ka + 6][ra] = ald1.z; As[nb][ka + 7][ra] = ald1.w;
            *(float4*)&Bs[nb][rb][cb] = bld0;
            *(float4*)&Bs[nb][rb][cb + 4] = bld1;
        }
        __syncthreads();
    }

    // ---- epilogue: bias + RoPE, write to g_qk ----
    const int colbase = bn * 128;
    const int rowbase = bm * 128;

    float bc[8];
    #pragma unroll
    for (int j = 0; j < 8; ++j) {
        int c = (j < 4) ? (tx * 4 + j) : (64 + tx * 4 + (j - 4));
        bc[j] = bias[colbase + c];
    }
    const int dbase = tx * 4;   // d index (same for both halves)

    #pragma unroll
    for (int r = 0; r < 8; ++r) {
        const int rl = (r < 4) ? (ty * 4 + r) : (64 + ty * 4 + (r - 4));
        const int m = rowbase + rl;
        const int s = m & (Sv - 1);
        float4 cs = *(const float4*)&g_cos[s * Dv + dbase];
        float4 sn = *(const float4*)&g_sin[s * Dv + dbase];
        #pragma unroll
        for (int g = 0; g < 2; ++g) {
            float v0 = acc[r][g * 4 + 0] + bc[g * 4 + 0];
            float v1 = acc[r][g * 4 + 1] + bc[g * 4 + 1];
            float v2 = acc[r][g * 4 + 2] + bc[g * 4 + 2];
            float v3 = acc[r][g * 4 + 3] + bc[g * 4 + 3];
            float4 o;
            o.x = v0 * cs.x - v1 * sn.x;
            o.y = v1 * cs.y + v0 * sn.y;
            o.z = v2 * cs.z - v3 * sn.z;
            o.w = v3 * cs.w + v2 * sn.w;
            *(float4*)&g_qk[(size_t)m * NQK + colbase + g * 64 + tx * 4] = o;
        }
    }
}

// ---------------------------------------------------------------------------
// GEMM2: per (b,h) logits[m,n] = sum_d q[m,d]*k[n,d], fused mask epilogue.
// Grid (nt=2, mt=2, b*13+h). 128x128 tile, K=64 in two 32-deep smem chunks.
// ---------------------------------------------------------------------------
__global__ __launch_bounds__(256) void attn_mask_kernel(
    const float* __restrict__ mask,
    float* __restrict__ out)
{
    __shared__ float Qs[32][128];      // [k][m]
    __shared__ float Ks[32][128];      // [k][n]

    const int bh = blockIdx.z;         // b*13 + h
    const int b  = bh / Tv;
    const int h  = bh - b * Tv;
    const int mt = blockIdx.y;
    const int nt = blockIdx.x;
    const int tid = threadIdx.x;
    const int tx = tid & 15;
    const int ty = tid >> 4;

    const int mrow_g = b * Sv + mt * 128;   // g_qk row base for Q
    const int nrow_g = b * Sv + nt * 128;   // g_qk row base for K
    const int qcol = h * 128;               // q at +0, k at +64

    float acc[8][8];
    #pragma unroll
    for (int i = 0; i < 8; ++i)
        #pragma unroll
        for (int j = 0; j < 8; ++j) acc[i][j] = 0.f;

    const int r  = tid >> 1;           // 0..127
    const int kh = (tid & 1) * 16;     // 0 or 16

    for (int k0 = 0; k0 < Dv; k0 += 32) {
        __syncthreads();
        const float* qp = g_qk + (size_t)(mrow_g + r) * NQK + qcol + k0 + kh;
        const float* kp = g_qk + (size_t)(nrow_g + r) * NQK + qcol + 64 + k0 + kh;
        #pragma unroll
        for (int u = 0; u < 4; ++u) {
            float4 qv = *(const float4*)(qp + u * 4);
            float4 kv = *(const float4*)(kp + u * 4);
            Qs[kh + u * 4 + 0][r] = qv.x; Qs[kh + u * 4 + 1][r] = qv.y;
            Qs[kh + u * 4 + 2][r] = qv.z; Qs[kh + u * 4 + 3][r] = qv.w;
            Ks[kh + u * 4 + 0][r] = kv.x; Ks[kh + u * 4 + 1][r] = kv.y;
            Ks[kh + u * 4 + 2][r] = kv.z; Ks[kh + u * 4 + 3][r] = kv.w;
        }
        __syncthreads();
        #pragma unroll
        for (int kk = 0; kk < 32; ++kk) {
            float a[8], bb[8];
            *(float4*)&a[0]  = *(float4*)&Qs[kk][ty * 4];
            *(float4*)&a[4]  = *(float4*)&Qs[kk][64 + ty * 4];
            *(float4*)&bb[0] = *(float4*)&Ks[kk][tx * 4];
            *(float4*)&bb[4] = *(float4*)&Ks[kk][64 + tx * 4];
            #pragma unroll
            for (int i = 0; i < 8; ++i)
                #pragma unroll
                for (int j = 0; j < 8; ++j)
                    acc[i][j] = fmaf(a[i], bb[j], acc[i][j]);
        }
    }

    // ---- epilogue: pad mask, causal (n < m), scale 1/8, matching ref op order ----
    int ncol[8];
    float pad[8];
    #pragma unroll
    for (int j = 0; j < 8; ++j) {
        int nl = (j < 4) ? (tx * 4 + j) : (64 + tx * 4 + (j - 4));
        ncol[j] = nt * 128 + nl;
        pad[j] = mask[b * Sv + ncol[j]];
    }

    #pragma unroll
    for (int i = 0; i < 8; ++i) {
        const int rl = (i < 4) ? (ty * 4 + i) : (64 + ty * 4 + (i - 4));
        const int m = mt * 128 + rl;
        float* op = out + ((size_t)bh * Sv + m) * Sv;
        float v[8];
        #pragma unroll
        for (int j = 0; j < 8; ++j) {
            float t = acc[i][j] * pad[j] - (1.0f - pad[j]) * NEGC;
            if (ncol[j] < m) t -= NEGC;
            v[j] = t * 0.125f;
        }
        float4 o0 = make_float4(v[0], v[1], v[2], v[3]);
        float4 o1 = make_float4(v[4], v[5], v[6], v[7]);
        *(float4*)(op + nt * 128 + tx * 4)      = o0;
        *(float4*)(op + nt * 128 + 64 + tx * 4) = o1;
    }
}

// ---------------------------------------------------------------------------
extern "C" void kernel_launch(void* const* d_in, const int* in_sizes, int n_in,
                              void* d_out, int out_size) {
    const float* X    = (const float*)d_in[0];   // last_hidden_state (64,256,768)
    const float* W    = (const float*)d_in[1];   // dense_w (768,1664)
    const float* bias = (const float*)d_in[2];   // dense_b (1664,)
    const float* mask = (const float*)d_in[3];   // attention_mask (64,256)
    float* out = (float*)d_out;                  // (64,13,256,256)

    rope_init_kernel<<<(Sv * Dv + 255) / 256, 256>>>();
    gemm1_rope_kernel<<<dim3(Tv, M1 / 128), 256>>>(X, W, bias);
    attn_mask_kernel<<<dim3(2, 2, Bv * Tv), 256>>>(mask, out);
}

// round 5
// speedup vs baseline: 5.0164x; 5.0163x over previous
#include <cuda_runtime.h>
#include <cuda_bf16.h>
#include <cstdint>

#define Bv 64
#define Sv 256
#define Hv 768
#define Tv 13
#define Dv 64
#define NQK 1664          /* T*2*D */
#define M1 16384          /* B*S */
#define NEGC 1000000000000.0f

// Scratch (static __device__ to satisfy allocation guards)
__device__ __nv_bfloat16 g_xb[(size_t)M1 * Hv];        // X in bf16        (25 MB)
__device__ __nv_bfloat16 g_wt[(size_t)NQK * Hv];       // W^T bf16, K-major (2.5 MB)
__device__ __nv_bfloat16 g_qkb[(size_t)M1 * NQK];      // RoPE'd q|k bf16  (54 MB)
__device__ float g_sin[Sv * Dv];
__device__ float g_cos[Sv * Dv];

#define SWZ(x) ((x) ^ (((x) >> 3) & 0x70))
#define GEMM1_SMEM 65536

static __device__ __forceinline__ uint32_t smem_u32(const void* p) {
    return (uint32_t)__cvta_generic_to_shared(p);
}

#define CP16(dst, src) \
    asm volatile("cp.async.cg.shared.global [%0], [%1], 16;" :: "r"(dst), "l"(src))
#define CP_COMMIT() asm volatile("cp.async.commit_group;" ::: "memory")
#define CP_WAIT(n)  asm volatile("cp.async.wait_group %0;" :: "n"(n) : "memory")

static __device__ __forceinline__ void ldsm4(uint32_t& r0, uint32_t& r1,
                                             uint32_t& r2, uint32_t& r3, uint32_t addr) {
    asm volatile("ldmatrix.sync.aligned.m8n8.x4.shared.b16 {%0,%1,%2,%3}, [%4];"
                 : "=r"(r0), "=r"(r1), "=r"(r2), "=r"(r3) : "r"(addr));
}
static __device__ __forceinline__ void mma_bf16(float* d, const uint32_t* a,
                                                const uint32_t* b) {
    asm volatile(
        "mma.sync.aligned.m16n8k16.row.col.f32.bf16.bf16.f32 "
        "{%0,%1,%2,%3}, {%4,%5,%6,%7}, {%8,%9}, {%0,%1,%2,%3};"
        : "+f"(d[0]), "+f"(d[1]), "+f"(d[2]), "+f"(d[3])
        : "r"(a[0]), "r"(a[1]), "r"(a[2]), "r"(a[3]), "r"(b[0]), "r"(b[1]));
}

// ---------------------------------------------------------------------------
__global__ void rope_init_kernel() {
    int idx = blockIdx.x * blockDim.x + threadIdx.x;
    if (idx >= Sv * Dv) return;
    int s = idx / Dv, d = idx % Dv, i = d >> 1;
    float inv = powf(10000.0f, -2.0f * (float)i / (float)Dv);
    float ang = (float)s * inv;
    g_sin[idx] = sinf(ang);
    g_cos[idx] = cosf(ang);
}

__global__ __launch_bounds__(256) void conv_x_kernel(const float* __restrict__ X) {
    int i = blockIdx.x * blockDim.x + threadIdx.x;   // one float4 per thread, exact grid
    float4 v = ((const float4*)X)[i];
    __nv_bfloat162 p0 = __floats2bfloat162_rn(v.x, v.y);
    __nv_bfloat162 p1 = __floats2bfloat162_rn(v.z, v.w);
    uint2 u;
    u.x = *(uint32_t*)&p0;
    u.y = *(uint32_t*)&p1;
    *(uint2*)(g_xb + (size_t)i * 4) = u;
}

__global__ void conv_w_kernel(const float* __restrict__ W) {
    __shared__ float s[32][33];
    int nb = blockIdx.x * 32, kb = blockIdx.y * 32;
    int tx = threadIdx.x, ty = threadIdx.y;
    s[ty][tx] = W[(size_t)(kb + ty) * NQK + nb + tx];
    __syncthreads();
    g_wt[(size_t)(nb + ty) * Hv + kb + tx] = __float2bfloat16(s[tx][ty]);
}

// ---------------------------------------------------------------------------
// GEMM1: C[16384,1664] = X @ W + b, RoPE epilogue -> g_qkb (bf16).
// 128x128 CTA tile, K-chunk 64 (SW128), 2-stage cp.async, mma.sync bf16.
// Dynamic smem: [stage][A 16KB | stage][B 16KB] = 64KB total.
// ---------------------------------------------------------------------------
__global__ __launch_bounds__(256) void gemm1_mma(const float* __restrict__ bias) {
    extern __shared__ __align__(1024) uint8_t dynsm[];
    // layout: A stage0 @0, A stage1 @16384, B stage0 @32768, B stage1 @49152
    const uint32_t sAb = smem_u32(dynsm);
    const uint32_t sBb = sAb + 32768;

    const int tid = threadIdx.x;
    const int wid = tid >> 5;
    const int lane = tid & 31;
    const int head = blockIdx.x;
    const int rowbase = blockIdx.y * 128;

    const int warp_m = wid & 1;        // 0/1 -> m offset 0/64
    const int warp_n = wid >> 1;       // 0..3 -> n offset *32

    // loader mapping: 256 threads, 4 rows each, 16B per row per operand
    const int r0 = tid >> 3, seg = tid & 7;
    const __nv_bfloat16* Abase = g_xb + (size_t)rowbase * Hv + seg * 8;
    const __nv_bfloat16* Bbase = g_wt + (size_t)(head * 128) * Hv + seg * 8;

    float acc[4][4][4];
    #pragma unroll
    for (int i = 0; i < 4; ++i)
        #pragma unroll
        for (int j = 0; j < 4; ++j)
            #pragma unroll
            for (int q = 0; q < 4; ++q) acc[i][j][q] = 0.f;

    // prefetch chunk 0
    #pragma unroll
    for (int t = 0; t < 4; ++t) {
        const int row = r0 + t * 32;
        const uint32_t off = SWZ(row * 128 + seg * 16);
        CP16(sAb + off, Abase + (size_t)row * Hv);
        CP16(sBb + off, Bbase + (size_t)row * Hv);
    }
    CP_COMMIT();

    const int lrow = lane & 15;                 // ldmatrix row within 16-block
    const int lcol16 = (lane >> 4) * 16;        // 0 / 16 bytes (k0 / k8)

    for (int c = 0; c < 12; ++c) {
        if (c + 1 < 12) {
            const int k0 = (c + 1) * 64;
            const uint32_t aDst = sAb + ((c + 1) & 1) * 16384;
            const uint32_t bDst = sBb + ((c + 1) & 1) * 16384;
            #pragma unroll
            for (int t = 0; t < 4; ++t) {
                const int row = r0 + t * 32;
                const uint32_t off = SWZ(row * 128 + seg * 16);
                CP16(aDst + off, Abase + (size_t)row * Hv + k0);
                CP16(bDst + off, Bbase + (size_t)row * Hv + k0);
            }
            CP_COMMIT();
            CP_WAIT(1);
        } else {
            CP_WAIT(0);
        }
        __syncthreads();

        const uint32_t aBase = sAb + (c & 1) * 16384;
        const uint32_t bBase = sBb + (c & 1) * 16384;
        #pragma unroll
        for (int ks = 0; ks < 4; ++ks) {
            const int kbyte = ks * 32 + lcol16;
            uint32_t bfr[4][2];
            #pragma unroll
            for (int nf2 = 0; nf2 < 2; ++nf2) {
                const int rowB = warp_n * 32 + nf2 * 16 + lrow;
                uint32_t b0, b1, b2, b3;
                ldsm4(b0, b1, b2, b3, bBase + SWZ(rowB * 128 + kbyte));
                bfr[2 * nf2][0] = b0; bfr[2 * nf2][1] = b2;
                bfr[2 * nf2 + 1][0] = b1; bfr[2 * nf2 + 1][1] = b3;
            }
            #pragma unroll
            for (int mf = 0; mf < 4; ++mf) {
                const int rowA = warp_m * 64 + mf * 16 + lrow;
                uint32_t a[4];
                ldsm4(a[0], a[1], a[2], a[3], aBase + SWZ(rowA * 128 + kbyte));
                #pragma unroll
                for (int nf = 0; nf < 4; ++nf)
                    mma_bf16(acc[mf][nf], a, bfr[nf]);
            }
        }
        __syncthreads();
    }

    // ---- epilogue: bias + RoPE -> bf16 ----
    const int gid = lane >> 2, tig = lane & 3;
    float b0v[4], b1v[4];
    #pragma unroll
    for (int nf = 0; nf < 4; ++nf) {
        const int cl = warp_n * 32 + nf * 8 + tig * 2;
        b0v[nf] = bias[head * 128 + cl];
        b1v[nf] = bias[head * 128 + cl + 1];
    }
    #pragma unroll
    for (int mf = 0; mf < 4; ++mf) {
        #pragma unroll
        for (int h = 0; h < 2; ++h) {
            const int row_l = warp_m * 64 + mf * 16 + gid + 8 * h;
            const int m = rowbase + row_l;
            const int s = m & (Sv - 1);
            #pragma unroll
            for (int nf = 0; nf < 4; ++nf) {
                const int col_l = warp_n * 32 + nf * 8 + tig * 2;
                const int d = col_l & 63;
                float v0 = acc[mf][nf][h * 2]     + b0v[nf];
                float v1 = acc[mf][nf][h * 2 + 1] + b1v[nf];
                float cs = g_cos[s * Dv + d];
                float sn = g_sin[s * Dv + d];
                float o0 = v0 * cs - v1 * sn;
                float o1 = v1 * cs + v0 * sn;
                __nv_bfloat162 p = __floats2bfloat162_rn(o0, o1);
                *(uint32_t*)(g_qkb + (size_t)m * NQK + head * 128 + col_l) =
                    *(uint32_t*)&p;
            }
        }
    }
}

// ---------------------------------------------------------------------------
// GEMM2: per (b,h) logits = q.k^T, fused mask epilogue (fp32).
// Grid (2,2,832). 128x128 tile, single K=64 stage. 32KB static smem.
// ---------------------------------------------------------------------------
__global__ __launch_bounds__(256) void attn_mma(const float* __restrict__ mask,
                                                float* __restrict__ out) {
    __shared__ __align__(1024) uint8_t sQ[16384];
    __shared__ __align__(1024) uint8_t sK[16384];

    const int tid = threadIdx.x;
    const int wid = tid >> 5;
    const int lane = tid & 31;
    const int nt = blockIdx.x, mt = blockIdx.y, bh = blockIdx.z;
    const int b = bh / Tv, h = bh - b * Tv;

    const int warp_m = wid & 1;
    const int warp_n = wid >> 1;

    const uint32_t sQb = smem_u32(sQ);
    const uint32_t sKb = smem_u32(sK);

    const int r0 = tid >> 3, seg = tid & 7;
    const __nv_bfloat16* Qg = g_qkb + (size_t)(b * Sv + mt * 128) * NQK + h * 128 + seg * 8;
    const __nv_bfloat16* Kg = g_qkb + (size_t)(b * Sv + nt * 128) * NQK + h * 128 + 64 + seg * 8;
    #pragma unroll
    for (int t = 0; t < 4; ++t) {
        const int row = r0 + t * 32;
        const uint32_t off = SWZ(row * 128 + seg * 16);
        CP16(sQb + off, Qg + (size_t)row * NQK);
        CP16(sKb + off, Kg + (size_t)row * NQK);
    }
    CP_COMMIT();
    CP_WAIT(0);
    __syncthreads();

    float acc[4][4][4];
    #pragma unroll
    for (int i = 0; i < 4; ++i)
        #pragma unroll
        for (int j = 0; j < 4; ++j)
            #pragma unroll
            for (int q = 0; q < 4; ++q) acc[i][j][q] = 0.f;

    const int lrow = lane & 15;
    const int lcol16 = (lane >> 4) * 16;
    #pragma unroll
    for (int ks = 0; ks < 4; ++ks) {
        const int kbyte = ks * 32 + lcol16;
        uint32_t bfr[4][2];
        #pragma unroll
        for (int nf2 = 0; nf2 < 2; ++nf2) {
            const int rowB = warp_n * 32 + nf2 * 16 + lrow;
            uint32_t b0, b1, b2, b3;
            ldsm4(b0, b1, b2, b3, sKb + SWZ(rowB * 128 + kbyte));
            bfr[2 * nf2][0] = b0; bfr[2 * nf2][1] = b2;
            bfr[2 * nf2 + 1][0] = b1; bfr[2 * nf2 + 1][1] = b3;
        }
        #pragma unroll
        for (int mf = 0; mf < 4; ++mf) {
            const int rowA = warp_m * 64 + mf * 16 + lrow;
            uint32_t a[4];
            ldsm4(a[0], a[1], a[2], a[3], sQb + SWZ(rowA * 128 + kbyte));
            #pragma unroll
            for (int nf = 0; nf < 4; ++nf)
                mma_bf16(acc[mf][nf], a, bfr[nf]);
        }
    }

    // ---- epilogue: pad mask, causal, scale, matching ref op order ----
    const int gid = lane >> 2, tig = lane & 3;
    float pad0[4], pad1[4];
    int ncol[4];
    #pragma unroll
    for (int nf = 0; nf < 4; ++nf) {
        const int n = nt * 128 + warp_n * 32 + nf * 8 + tig * 2;
        ncol[nf] = n;
        pad0[nf] = mask[b * Sv + n];
        pad1[nf] = mask[b * Sv + n + 1];
    }
    #pragma unroll
    for (int mf = 0; mf < 4; ++mf) {
        #pragma unroll
        for (int h = 0; h < 2; ++h) {
            const int m = mt * 128 + warp_m * 64 + mf * 16 + gid + 8 * h;
            float* orow = out + ((size_t)bh * Sv + m) * Sv;
            #pragma unroll
            for (int nf = 0; nf < 4; ++nf) {
                const int n = ncol[nf];
                float t0 = acc[mf][nf][h * 2]     * pad0[nf] - (1.0f - pad0[nf]) * NEGC;
                float t1 = acc[mf][nf][h * 2 + 1] * pad1[nf] - (1.0f - pad1[nf]) * NEGC;
                if (n < m)     t0 -= NEGC;
                if (n + 1 < m) t1 -= NEGC;
                float2 o = make_float2(t0 * 0.125f, t1 * 0.125f);
                *(float2*)(orow + n) = o;
            }
        }
    }
}

// ---------------------------------------------------------------------------
extern "C" void kernel_launch(void* const* d_in, const int* in_sizes, int n_in,
                              void* d_out, int out_size) {
    const float* X    = (const float*)d_in[0];   // (64,256,768)
    const float* W    = (const float*)d_in[1];   // (768,1664)
    const float* bias = (const float*)d_in[2];   // (1664,)
    const float* mask = (const float*)d_in[3];   // (64,256)
    float* out = (float*)d_out;                  // (64,13,256,256)

    cudaFuncSetAttribute(gemm1_mma,
                         cudaFuncAttributeMaxDynamicSharedMemorySize, GEMM1_SMEM);

    rope_init_kernel<<<(Sv * Dv + 255) / 256, 256>>>();
    conv_x_kernel<<<(M1 * Hv / 4) / 256, 256>>>(X);
    conv_w_kernel<<<dim3(NQK / 32, Hv / 32), dim3(32, 32)>>>(W);
    gemm1_mma<<<dim3(Tv, M1 / 128), 256, GEMM1_SMEM>>>(bias);
    attn_mma<<<dim3(2, 2, Bv * Tv), 256>>>(mask, out);
}